// round 2
// baseline (speedup 1.0000x reference)
#include <cuda_runtime.h>
#include <math.h>

#define Bq 2
#define Dq 256
#define Hq 8
#define Tq 128
#define Fq 64
#define Cq 512
#define TEq 512
#define NDIST 255   // pd in [-127,127]

// ---------------- scratch (device globals; no allocation allowed) ----------
__device__ float g_tp [Bq * Tq * Cq];          // time projection (B,T,C)      0.5 MB
__device__ float g_lut[NDIST * Cq];            // dist-emb LUT (255,C)         0.5 MB
__device__ float g_act[Bq * Tq * Tq * Cq];     // silu(emb)  (B,T,S,C)          67 MB
__device__ float g_R  [Bq * Tq * Tq * Cq];     // R          (B,T,S,C)          67 MB

// ---------------- kernel 1: time_proj = temb @ w_time + b_time -------------
// one block per (b,t); 512 threads, one output channel each
__global__ void tp_kernel(const float* __restrict__ temb,
                          const float* __restrict__ w_time,
                          const float* __restrict__ b_time) {
    __shared__ float tr[TEq];
    int bt = blockIdx.x;           // 0..B*T-1
    int c  = threadIdx.x;          // 0..511
    tr[c] = temb[bt * TEq + c];
    __syncthreads();
    float acc = b_time[c];
    #pragma unroll 8
    for (int k = 0; k < TEq; k++)
        acc += tr[k] * w_time[k * Cq + c];
    g_tp[bt * Cq + c] = acc;
}

// ---------------- kernel 2: dist LUT ---------------------------------------
__global__ void lut_kernel(const float* __restrict__ w_dist,
                           const float* __restrict__ b_dist) {
    int didx = blockIdx.x;         // 0..254
    int c    = threadIdx.x;        // 0..511
    float d  = (float)(didx - (Tq - 1));
    float e0 = log1pf(fmaxf(d, 0.0f));
    float e1 = log1pf(fmaxf(-d, 0.0f));
    float e2 = (didx == (Tq - 1)) ? 1.0f : 0.0f;
    g_lut[didx * Cq + c] = e0 * w_dist[0 * Cq + c]
                         + e1 * w_dist[1 * Cq + c]
                         + e2 * w_dist[2 * Cq + c]
                         + b_dist[c];
}

// ---------------- kernel 3: act = silu(tp + lut[pd]) ------------------------
__global__ void act_kernel(const int* __restrict__ pd) {
    long long e = (long long)blockIdx.x * blockDim.x + threadIdx.x;
    // e indexes (b,t,s,c) flattened; total = B*T*T*C = 16,777,216
    int c  = (int)(e & (Cq - 1));
    long long r = e >> 9;          // (b,t,s)
    int s  = (int)(r % Tq);
    long long bt = r / Tq;         // b*T + t
    int didx = pd[bt * Tq + s] + (Tq - 1);
    float x = g_tp[bt * Cq + c] + g_lut[didx * Cq + c];
    g_act[e] = x / (1.0f + expf(-x));
}

// ---------------- kernel 4: R = act @ w_out + b_out -------------------------
// M = 32768, N = 512, K = 512. 128x128x8 tiles, 256 threads, 8x8 microtile.
__global__ __launch_bounds__(256) void gemmR_kernel(const float* __restrict__ w_out,
                                                    const float* __restrict__ b_out) {
    __shared__ float As[8][128];
    __shared__ float Bs[8][128];
    const int K = Cq;
    int bn = blockIdx.x;           // 0..3
    int bm = blockIdx.y;           // 0..255
    int tid = threadIdx.x;
    int tx = tid & 15;             // N dir
    int ty = tid >> 4;             // M dir
    float acc[8][8] = {};
    const float* Aptr = g_act + (size_t)bm * 128 * K;

    int a_m  = tid >> 1;
    int a_k4 = (tid & 1) * 4;
    int b_k  = tid >> 5;
    int b_n4 = (tid & 31) * 4;

    for (int k0 = 0; k0 < K; k0 += 8) {
        float4 av = *(const float4*)(Aptr + (size_t)a_m * K + k0 + a_k4);
        As[a_k4 + 0][a_m] = av.x; As[a_k4 + 1][a_m] = av.y;
        As[a_k4 + 2][a_m] = av.z; As[a_k4 + 3][a_m] = av.w;
        float4 bv = *(const float4*)(w_out + (size_t)(k0 + b_k) * Cq + bn * 128 + b_n4);
        *(float4*)&Bs[b_k][b_n4] = bv;
        __syncthreads();
        #pragma unroll
        for (int k = 0; k < 8; k++) {
            float4 a0 = *(float4*)&As[k][ty * 8];
            float4 a1 = *(float4*)&As[k][ty * 8 + 4];
            float4 b0 = *(float4*)&Bs[k][tx * 8];
            float4 b1 = *(float4*)&Bs[k][tx * 8 + 4];
            float a[8] = {a0.x,a0.y,a0.z,a0.w,a1.x,a1.y,a1.z,a1.w};
            float b[8] = {b0.x,b0.y,b0.z,b0.w,b1.x,b1.y,b1.z,b1.w};
            #pragma unroll
            for (int i = 0; i < 8; i++)
                #pragma unroll
                for (int j = 0; j < 8; j++)
                    acc[i][j] += a[i] * b[j];
        }
        __syncthreads();
    }
    #pragma unroll
    for (int i = 0; i < 8; i++) {
        size_t m = (size_t)bm * 128 + ty * 8 + i;
        #pragma unroll
        for (int j = 0; j < 8; j += 4) {
            int n = bn * 128 + tx * 8 + j;
            float4 v;
            v.x = acc[i][j + 0] + b_out[n + 0];
            v.y = acc[i][j + 1] + b_out[n + 1];
            v.z = acc[i][j + 2] + b_out[n + 2];
            v.w = acc[i][j + 3] + b_out[n + 3];
            *(float4*)(g_R + m * Cq + n) = v;
        }
    }
}

// ---------------- kernel 5: out[b,d,h,t,s] = sum_f qk[b,d,h,t,f]*R[b,t,s,h,f]
// per block: one (b,h,t,dchunk); 64 d-rows x 128 s-cols, K=F=64 in 2 chunks of 32
__global__ __launch_bounds__(256) void einsum_kernel(const float* __restrict__ qk,
                                                     float* __restrict__ out) {
    __shared__ float As[32][65];    // [f][d]
    __shared__ float Bs[32][129];   // [f][s]
    int bid = blockIdx.x;           // B*H*T*4 = 8192
    int dchunk = bid & 3;  int rest = bid >> 2;
    int t = rest % Tq;     rest /= Tq;
    int h = rest % Hq;     int b = rest / Hq;

    int tid = threadIdx.x;
    int tx = tid & 15;              // s dir
    int ty = tid >> 4;              // d dir
    float acc[4][8] = {};

    const size_t qk_dstride = (size_t)Hq * Tq * Fq;
    const float* qk_base = qk + ((((size_t)b * Dq + dchunk * 64) * Hq + h) * Tq + t) * Fq;
    const float* R_base  = g_R + ((size_t)(b * Tq + t) * Tq) * Cq + h * Fq;

    #pragma unroll
    for (int kc = 0; kc < 2; kc++) {
        #pragma unroll
        for (int r = 0; r < 2; r++) {
            int idx = tid + r * 256;          // 0..511 -> 64 rows x 8 float4
            int d = idx >> 3; int f4 = (idx & 7) * 4;
            float4 v = *(const float4*)(qk_base + (size_t)d * qk_dstride + kc * 32 + f4);
            As[f4 + 0][d] = v.x; As[f4 + 1][d] = v.y;
            As[f4 + 2][d] = v.z; As[f4 + 3][d] = v.w;
        }
        #pragma unroll
        for (int r = 0; r < 4; r++) {
            int idx = tid + r * 256;          // 0..1023 -> 128 rows x 8 float4
            int s = idx >> 3; int f4 = (idx & 7) * 4;
            float4 v = *(const float4*)(R_base + (size_t)s * Cq + kc * 32 + f4);
            Bs[f4 + 0][s] = v.x; Bs[f4 + 1][s] = v.y;
            Bs[f4 + 2][s] = v.z; Bs[f4 + 3][s] = v.w;
        }
        __syncthreads();
        #pragma unroll
        for (int k = 0; k < 32; k++) {
            float a[4], bb[8];
            #pragma unroll
            for (int i = 0; i < 4; i++) a[i] = As[k][ty + i * 16];
            #pragma unroll
            for (int j = 0; j < 8; j++) bb[j] = Bs[k][tx + j * 16];
            #pragma unroll
            for (int i = 0; i < 4; i++)
                #pragma unroll
                for (int j = 0; j < 8; j++)
                    acc[i][j] += a[i] * bb[j];
        }
        __syncthreads();
    }

    const size_t out_dstride = (size_t)Hq * Tq * Tq;
    float* out_base = out + ((((size_t)b * Dq + dchunk * 64) * Hq + h) * Tq + t) * Tq;
    #pragma unroll
    for (int i = 0; i < 4; i++) {
        int d = ty + i * 16;
        #pragma unroll
        for (int j = 0; j < 8; j++)
            out_base[(size_t)d * out_dstride + tx + j * 16] = acc[i][j];
    }
}

// ---------------------------------------------------------------------------
extern "C" void kernel_launch(void* const* d_in, const int* in_sizes, int n_in,
                              void* d_out, int out_size) {
    const float* qk     = (const float*)d_in[0];
    const float* temb   = (const float*)d_in[1];
    const int*   pd     = (const int*)  d_in[2];
    const float* w_dist = (const float*)d_in[3];
    const float* b_dist = (const float*)d_in[4];
    const float* w_time = (const float*)d_in[5];
    const float* b_time = (const float*)d_in[6];
    const float* w_out  = (const float*)d_in[7];
    const float* b_out  = (const float*)d_in[8];
    float* out = (float*)d_out;

    tp_kernel <<<Bq * Tq, Cq>>>(temb, w_time, b_time);
    lut_kernel<<<NDIST,  Cq>>>(w_dist, b_dist);
    act_kernel<<<(Bq * Tq * Tq * Cq) / 256, 256>>>(pd);
    dim3 gR(Cq / 128, (Bq * Tq * Tq) / 128);
    gemmR_kernel<<<gR, 256>>>(w_out, b_out);
    einsum_kernel<<<Bq * Hq * Tq * (Dq / 64), 256>>>(qk, out);
}

// round 3
// speedup vs baseline: 2.1176x; 2.1176x over previous
#include <cuda_runtime.h>
#include <math.h>

#define Bq 2
#define Dq 256
#define Hq 8
#define Tq 128
#define Fq 64
#define Cq 512
#define TEq 512
#define NDIST 255   // pd in [-127,127]

// ---------------- scratch (device globals; no allocation allowed) ----------
__device__ float g_tp [Bq * Tq * Cq];          // time projection (B,T,C)      0.5 MB
__device__ float g_lut[NDIST * Cq];            // dist-emb LUT (255,C)         0.5 MB
__device__ float g_R  [Bq * Tq * Tq * Cq];     // R (B,T,S,C)                   67 MB

// ---------------- tf32 helpers ----------------------------------------------
__device__ __forceinline__ unsigned f2tf32(float x) {
    unsigned r;
    asm("cvt.rna.tf32.f32 %0, %1;" : "=r"(r) : "f"(x));
    return r;
}

__device__ __forceinline__ void mma8(float c[4],
                                     const unsigned a[4],
                                     unsigned b0, unsigned b1) {
    asm volatile(
        "mma.sync.aligned.m16n8k8.row.col.f32.tf32.tf32.f32 "
        "{%0,%1,%2,%3}, {%4,%5,%6,%7}, {%8,%9}, {%0,%1,%2,%3};"
        : "+f"(c[0]), "+f"(c[1]), "+f"(c[2]), "+f"(c[3])
        : "r"(a[0]), "r"(a[1]), "r"(a[2]), "r"(a[3]), "r"(b0), "r"(b1));
}

__device__ __forceinline__ float silu(float x) {
    return x / (1.0f + __expf(-x));
}

// ---------------- kernel 1: time_proj = temb @ w_time + b_time -------------
__global__ void tp_kernel(const float* __restrict__ temb,
                          const float* __restrict__ w_time,
                          const float* __restrict__ b_time) {
    __shared__ float tr[TEq];
    int bt = blockIdx.x;
    int c  = threadIdx.x;
    tr[c] = temb[bt * TEq + c];
    __syncthreads();
    float acc = b_time[c];
    #pragma unroll 8
    for (int k = 0; k < TEq; k++)
        acc += tr[k] * w_time[k * Cq + c];
    g_tp[bt * Cq + c] = acc;
}

// ---------------- kernel 2: dist LUT ---------------------------------------
__global__ void lut_kernel(const float* __restrict__ w_dist,
                           const float* __restrict__ b_dist) {
    int didx = blockIdx.x;         // 0..254
    int c    = threadIdx.x;        // 0..511
    float d  = (float)(didx - (Tq - 1));
    float e0 = log1pf(fmaxf(d, 0.0f));
    float e1 = log1pf(fmaxf(-d, 0.0f));
    float e2 = (didx == (Tq - 1)) ? 1.0f : 0.0f;
    g_lut[didx * Cq + c] = e0 * w_dist[0 * Cq + c]
                         + e1 * w_dist[1 * Cq + c]
                         + e2 * w_dist[2 * Cq + c]
                         + b_dist[c];
}

// ---------------- kernel 3: R = silu(tp + lut[pd]) @ w_out + b_out (tf32 MMA)
// M = 32768 (bt*128+s), N = 512, K = 512. Block 128x128, K-chunk 32.
// A fused on load: silu(tp[bt][k] + lut[didx[s]][k]).
// Smem layouts: As[m][k] (stride 36), Bs[n][k] (stride 36) — conflict-free frags.
__global__ __launch_bounds__(256) void gemmR_tc(const int* __restrict__ pd,
                                                const float* __restrict__ w_out,
                                                const float* __restrict__ b_out) {
    __shared__ unsigned As[128][36];
    __shared__ unsigned Bs[128][36];
    __shared__ int   sdid[128];
    __shared__ float stp[512];
    __shared__ float sbo[128];

    int tid = threadIdx.x;
    int bn = blockIdx.x;           // 0..3 (N tile)
    int bt = blockIdx.y;           // 0..255 (one (b,t) pair = 128 M rows)

    if (tid < 128) sdid[tid] = pd[bt * 128 + tid] + (Tq - 1);
    stp[tid]       = g_tp[bt * Cq + tid];
    stp[tid + 256] = g_tp[bt * Cq + tid + 256];
    if (tid < 128) sbo[tid] = b_out[bn * 128 + tid];
    __syncthreads();

    int lane = tid & 31, warp = tid >> 5;
    int g = lane >> 2, tig = lane & 3;
    int wm = warp >> 1, wn = warp & 1;
    int mbase = wm * 32, nbase = wn * 64;

    float acc[2][8][4] = {};

    for (int k0 = 0; k0 < Cq; k0 += 32) {
        // A tile: 128 s x 32 k. idx -> s=idx>>3, k4=(idx&7)*4. Coalesced lut read.
        #pragma unroll
        for (int r = 0; r < 4; ++r) {
            int idx = tid + r * 256;
            int s = idx >> 3, k4 = (idx & 7) * 4;
            float4 v = *(const float4*)(g_lut + (size_t)sdid[s] * Cq + k0 + k4);
            float x0 = stp[k0 + k4 + 0] + v.x;
            float x1 = stp[k0 + k4 + 1] + v.y;
            float x2 = stp[k0 + k4 + 2] + v.z;
            float x3 = stp[k0 + k4 + 3] + v.w;
            uint4 o;
            o.x = f2tf32(silu(x0)); o.y = f2tf32(silu(x1));
            o.z = f2tf32(silu(x2)); o.w = f2tf32(silu(x3));
            *(uint4*)&As[s][k4] = o;
        }
        // B tile: w_out[k][n] -> Bs[n][k]. idx -> n=idx&127, kq=idx>>7.
        // 4 coalesced scalar LDG (128B/warp each), one STS.128.
        #pragma unroll
        for (int r = 0; r < 4; ++r) {
            int idx = tid + r * 256;
            int n = idx & 127, kq = idx >> 7;
            const float* wp = w_out + (size_t)(k0 + kq * 4) * Cq + bn * 128 + n;
            uint4 o;
            o.x = f2tf32(wp[0 * Cq]);
            o.y = f2tf32(wp[1 * Cq]);
            o.z = f2tf32(wp[2 * Cq]);
            o.w = f2tf32(wp[3 * Cq]);
            *(uint4*)&Bs[n][kq * 4] = o;
        }
        __syncthreads();
        #pragma unroll
        for (int q = 0; q < 4; ++q) {
            int kk = q * 8;
            unsigned a[2][4];
            #pragma unroll
            for (int mt = 0; mt < 2; ++mt) {
                int m = mbase + mt * 16 + g;
                a[mt][0] = As[m][kk + tig];
                a[mt][1] = As[m + 8][kk + tig];
                a[mt][2] = As[m][kk + tig + 4];
                a[mt][3] = As[m + 8][kk + tig + 4];
            }
            #pragma unroll
            for (int nt = 0; nt < 8; ++nt) {
                int n = nbase + nt * 8 + g;
                unsigned b0 = Bs[n][kk + tig];
                unsigned b1 = Bs[n][kk + tig + 4];
                mma8(acc[0][nt], a[0], b0, b1);
                mma8(acc[1][nt], a[1], b0, b1);
            }
        }
        __syncthreads();
    }

    // epilogue: R[m][n] = acc + b_out[n]
    size_t Rbase = (size_t)bt * 128 * Cq + bn * 128;
    #pragma unroll
    for (int mt = 0; mt < 2; ++mt) {
        int r0 = mbase + mt * 16 + g;
        #pragma unroll
        for (int nt = 0; nt < 8; ++nt) {
            int nl = nbase + nt * 8 + 2 * tig;
            float2 v0 = make_float2(acc[mt][nt][0] + sbo[nl],
                                    acc[mt][nt][1] + sbo[nl + 1]);
            float2 v1 = make_float2(acc[mt][nt][2] + sbo[nl],
                                    acc[mt][nt][3] + sbo[nl + 1]);
            *(float2*)(g_R + Rbase + (size_t)r0 * Cq + nl)       = v0;
            *(float2*)(g_R + Rbase + (size_t)(r0 + 8) * Cq + nl) = v1;
        }
    }
}

// ---------------- kernel 4: out[b,d,h,t,s] = sum_f qk[b,d,h,t,f]*R[b,t,s,h,f]
// per block: one (b,h,t,dchunk). M=128 (d), N=128 (s), K=64 (f), whole K in smem.
__global__ __launch_bounds__(256) void einsum_tc(const float* __restrict__ qk,
                                                 float* __restrict__ out) {
    __shared__ unsigned As[128][68];   // [d][f]
    __shared__ unsigned Bs[128][68];   // [s][f]

    int tid = threadIdx.x;
    int bid = blockIdx.x;              // B*H*T*2 = 4096
    int dchunk = bid & 1; int rest = bid >> 1;
    int t = rest & 127; rest >>= 7;
    int h = rest & 7;   int b = rest >> 3;

    const size_t dstr = (size_t)Hq * Tq * Fq;   // 65536
    const float* qk_base = qk + ((((size_t)b * Dq + dchunk * 128) * Hq + h) * Tq + t) * Fq;
    const float* R_base  = g_R + (size_t)(b * Tq + t) * Tq * Cq + h * Fq;

    // load A (128 d x 64 f) and B (128 s x 64 f): idx -> row=idx>>4, f4=(idx&15)*4
    #pragma unroll
    for (int r = 0; r < 8; ++r) {
        int idx = tid + r * 256;
        int row = idx >> 4, f4 = (idx & 15) * 4;
        float4 v = *(const float4*)(qk_base + (size_t)row * dstr + f4);
        uint4 o;
        o.x = f2tf32(v.x); o.y = f2tf32(v.y); o.z = f2tf32(v.z); o.w = f2tf32(v.w);
        *(uint4*)&As[row][f4] = o;
    }
    #pragma unroll
    for (int r = 0; r < 8; ++r) {
        int idx = tid + r * 256;
        int row = idx >> 4, f4 = (idx & 15) * 4;
        float4 v = *(const float4*)(R_base + (size_t)row * Cq + f4);
        uint4 o;
        o.x = f2tf32(v.x); o.y = f2tf32(v.y); o.z = f2tf32(v.z); o.w = f2tf32(v.w);
        *(uint4*)&Bs[row][f4] = o;
    }
    __syncthreads();

    int lane = tid & 31, warp = tid >> 5;
    int g = lane >> 2, tig = lane & 3;
    int wm = warp >> 1, wn = warp & 1;
    int mbase = wm * 32, nbase = wn * 64;

    float acc[2][8][4] = {};

    #pragma unroll
    for (int q = 0; q < 8; ++q) {
        int kk = q * 8;
        unsigned a[2][4];
        #pragma unroll
        for (int mt = 0; mt < 2; ++mt) {
            int m = mbase + mt * 16 + g;
            a[mt][0] = As[m][kk + tig];
            a[mt][1] = As[m + 8][kk + tig];
            a[mt][2] = As[m][kk + tig + 4];
            a[mt][3] = As[m + 8][kk + tig + 4];
        }
        #pragma unroll
        for (int nt = 0; nt < 8; ++nt) {
            int n = nbase + nt * 8 + g;
            unsigned b0 = Bs[n][kk + tig];
            unsigned b1 = Bs[n][kk + tig + 4];
            mma8(acc[0][nt], a[0], b0, b1);
            mma8(acc[1][nt], a[1], b0, b1);
        }
    }

    // epilogue: out[b, dchunk*128+row, h, t, s]
    const size_t ostr = (size_t)Hq * Tq * Tq;   // 131072
    float* out_base = out + ((((size_t)b * Dq + dchunk * 128) * Hq + h) * Tq + t) * Tq;
    #pragma unroll
    for (int mt = 0; mt < 2; ++mt) {
        int r0 = mbase + mt * 16 + g;
        #pragma unroll
        for (int nt = 0; nt < 8; ++nt) {
            int nl = nbase + nt * 8 + 2 * tig;
            *(float2*)(out_base + (size_t)r0 * ostr + nl) =
                make_float2(acc[mt][nt][0], acc[mt][nt][1]);
            *(float2*)(out_base + (size_t)(r0 + 8) * ostr + nl) =
                make_float2(acc[mt][nt][2], acc[mt][nt][3]);
        }
    }
}

// ---------------------------------------------------------------------------
extern "C" void kernel_launch(void* const* d_in, const int* in_sizes, int n_in,
                              void* d_out, int out_size) {
    const float* qk     = (const float*)d_in[0];
    const float* temb   = (const float*)d_in[1];
    const int*   pd     = (const int*)  d_in[2];
    const float* w_dist = (const float*)d_in[3];
    const float* b_dist = (const float*)d_in[4];
    const float* w_time = (const float*)d_in[5];
    const float* b_time = (const float*)d_in[6];
    const float* w_out  = (const float*)d_in[7];
    const float* b_out  = (const float*)d_in[8];
    float* out = (float*)d_out;

    tp_kernel <<<Bq * Tq, Cq>>>(temb, w_time, b_time);
    lut_kernel<<<NDIST,  Cq>>>(w_dist, b_dist);
    dim3 gR(Cq / 128, (Bq * Tq * Tq) / 128);
    gemmR_tc<<<gR, 256>>>(pd, w_out, b_out);
    einsum_tc<<<Bq * Hq * Tq * 2, 256>>>(qk, out);
}

// round 4
// speedup vs baseline: 2.4745x; 1.1685x over previous
#include <cuda_runtime.h>
#include <math.h>

#define Bq 2
#define Dq 256
#define Hq 8
#define Tq 128
#define Fq 64
#define Cq 512
#define TEq 512
#define NDIST 255   // pd in [-127,127]

// ---------------- scratch (device globals; no allocation allowed) ----------
__device__ float    g_tp [Bq * Tq * Cq];        // time projection (B,T,C)
__device__ float    g_lut[NDIST * Cq];          // dist-emb LUT (255,C)
__device__ unsigned g_Bk [Cq * Cq];             // w_out pre-converted to tf32, k-major
__device__ float    g_R  [Bq * Tq * Tq * Cq];   // R (B,T,S,C)   67 MB

// ---------------- tf32 helpers ----------------------------------------------
__device__ __forceinline__ unsigned f2tf32(float x) {
    unsigned r;
    asm("cvt.rna.tf32.f32 %0, %1;" : "=r"(r) : "f"(x));
    return r;
}

__device__ __forceinline__ void mma8(float c[4],
                                     const unsigned a[4],
                                     unsigned b0, unsigned b1) {
    asm volatile(
        "mma.sync.aligned.m16n8k8.row.col.f32.tf32.tf32.f32 "
        "{%0,%1,%2,%3}, {%4,%5,%6,%7}, {%8,%9}, {%0,%1,%2,%3};"
        : "+f"(c[0]), "+f"(c[1]), "+f"(c[2]), "+f"(c[3])
        : "r"(a[0]), "r"(a[1]), "r"(a[2]), "r"(a[3]), "r"(b0), "r"(b1));
}

__device__ __forceinline__ float silu(float x) {
    return x / (1.0f + __expf(-x));
}

__device__ __forceinline__ void cpa16(void* dst, const void* src) {
    unsigned d = (unsigned)__cvta_generic_to_shared(dst);
    asm volatile("cp.async.cg.shared.global [%0], [%1], 16;" :: "r"(d), "l"(src) : "memory");
}

// ---------------- kernel 1: time_proj = temb @ w_time + b_time -------------
__global__ void tp_kernel(const float* __restrict__ temb,
                          const float* __restrict__ w_time,
                          const float* __restrict__ b_time) {
    __shared__ float tr[TEq];
    int bt = blockIdx.x;
    int c  = threadIdx.x;
    tr[c] = temb[bt * TEq + c];
    __syncthreads();
    float acc = b_time[c];
    #pragma unroll 8
    for (int k = 0; k < TEq; k++)
        acc += tr[k] * w_time[k * Cq + c];
    g_tp[bt * Cq + c] = acc;
}

// ---------------- kernel 2: dist LUT ---------------------------------------
__global__ void lut_kernel(const float* __restrict__ w_dist,
                           const float* __restrict__ b_dist) {
    int didx = blockIdx.x;         // 0..254
    int c    = threadIdx.x;        // 0..511
    float d  = (float)(didx - (Tq - 1));
    float e0 = log1pf(fmaxf(d, 0.0f));
    float e1 = log1pf(fmaxf(-d, 0.0f));
    float e2 = (didx == (Tq - 1)) ? 1.0f : 0.0f;
    g_lut[didx * Cq + c] = e0 * w_dist[0 * Cq + c]
                         + e1 * w_dist[1 * Cq + c]
                         + e2 * w_dist[2 * Cq + c]
                         + b_dist[c];
}

// ---------------- kernel 2b: pre-convert w_out -> tf32 (k-major) ------------
__global__ void cvtB_kernel(const float* __restrict__ w_out) {
    int k = blockIdx.x, t = threadIdx.x;
    g_Bk[k * Cq + t]       = f2tf32(w_out[k * Cq + t]);
    g_Bk[k * Cq + t + 256] = f2tf32(w_out[k * Cq + t + 256]);
}

// ---------------- kernel 3: R = silu(tp + lut[pd]) @ w_out + b_out ----------
// M=32768, N=512, K=512. Block 128x128, K-chunk 32, double-buffered pipeline.
__global__ __launch_bounds__(256) void gemmR_tc(const int* __restrict__ pd,
                                                const float* __restrict__ b_out) {
    __shared__ unsigned As[2][128][36];   // [m][k], bank-free frag loads
    __shared__ unsigned Bs[2][32][136];   // [k][n], bank-free frag loads
    __shared__ int   sdid[128];
    __shared__ float stp[512];
    __shared__ float sbo[128];

    int tid = threadIdx.x;
    int bn = blockIdx.x;           // 0..3 (N tile)
    int bt = blockIdx.y;           // 0..255 (one (b,t) pair = 128 M rows)

    if (tid < 128) sdid[tid] = pd[bt * 128 + tid] + (Tq - 1);
    stp[tid]       = g_tp[bt * Cq + tid];
    stp[tid + 256] = g_tp[bt * Cq + tid + 256];
    if (tid < 128) sbo[tid] = b_out[bn * 128 + tid];
    __syncthreads();

    // per-thread A geometry: 4 rows, 4 consecutive k each
    int k4 = (tid & 7) * 4;
    int sRow[4];
    const float* lrow[4];
    #pragma unroll
    for (int r = 0; r < 4; ++r) {
        sRow[r] = (tid + r * 256) >> 3;
        lrow[r] = g_lut + (size_t)sdid[sRow[r]] * Cq + k4;
    }
    // per-thread B cp.async geometry: 4 rows (k), one 16B seg each
    int kbase = tid >> 5;          // 0..7
    int seg   = tid & 31;          // 0..31  (column seg*4 .. seg*4+3)
    const unsigned* Bsrc = g_Bk + bn * 128 + seg * 4;

    float4 areg[4];

    // ---- prologue: chunk 0 ----
    #pragma unroll
    for (int r = 0; r < 4; ++r)
        cpa16(&Bs[0][kbase + 8 * r][seg * 4],
              Bsrc + (size_t)(kbase + 8 * r) * Cq);
    asm volatile("cp.async.commit_group;" ::: "memory");
    #pragma unroll
    for (int r = 0; r < 4; ++r) areg[r] = *(const float4*)(lrow[r]);
    #pragma unroll
    for (int r = 0; r < 4; ++r) {
        uint4 o;
        o.x = f2tf32(silu(stp[k4 + 0] + areg[r].x));
        o.y = f2tf32(silu(stp[k4 + 1] + areg[r].y));
        o.z = f2tf32(silu(stp[k4 + 2] + areg[r].z));
        o.w = f2tf32(silu(stp[k4 + 3] + areg[r].w));
        *(uint4*)&As[0][sRow[r]][k4] = o;
    }
    asm volatile("cp.async.wait_group 0;" ::: "memory");
    __syncthreads();

    int lane = tid & 31, warp = tid >> 5;
    int g = lane >> 2, tig = lane & 3;
    int wm = warp >> 1, wn = warp & 1;
    int mbase = wm * 32, nbase = wn * 64;

    float acc[2][8][4] = {};

    for (int i = 0; i < 16; ++i) {
        int cur = i & 1, nxt = cur ^ 1;
        int k1 = (i + 1) * 32;
        if (i < 15) {
            #pragma unroll
            for (int r = 0; r < 4; ++r)
                cpa16(&Bs[nxt][kbase + 8 * r][seg * 4],
                      Bsrc + (size_t)(k1 + kbase + 8 * r) * Cq);
            asm volatile("cp.async.commit_group;" ::: "memory");
            #pragma unroll
            for (int r = 0; r < 4; ++r) areg[r] = *(const float4*)(lrow[r] + k1);
        }
        #pragma unroll
        for (int q = 0; q < 4; ++q) {
            int kk = q * 8;
            unsigned a[2][4];
            #pragma unroll
            for (int mt = 0; mt < 2; ++mt) {
                int m = mbase + mt * 16 + g;
                a[mt][0] = As[cur][m][kk + tig];
                a[mt][1] = As[cur][m + 8][kk + tig];
                a[mt][2] = As[cur][m][kk + tig + 4];
                a[mt][3] = As[cur][m + 8][kk + tig + 4];
            }
            #pragma unroll
            for (int nt = 0; nt < 8; ++nt) {
                int n = nbase + nt * 8 + g;
                unsigned b0 = Bs[cur][kk + tig][n];
                unsigned b1 = Bs[cur][kk + tig + 4][n];
                mma8(acc[0][nt], a[0], b0, b1);
                mma8(acc[1][nt], a[1], b0, b1);
            }
        }
        if (i < 15) {
            #pragma unroll
            for (int r = 0; r < 4; ++r) {
                uint4 o;
                o.x = f2tf32(silu(stp[k1 + k4 + 0] + areg[r].x));
                o.y = f2tf32(silu(stp[k1 + k4 + 1] + areg[r].y));
                o.z = f2tf32(silu(stp[k1 + k4 + 2] + areg[r].z));
                o.w = f2tf32(silu(stp[k1 + k4 + 3] + areg[r].w));
                *(uint4*)&As[nxt][sRow[r]][k4] = o;
            }
            asm volatile("cp.async.wait_group 0;" ::: "memory");
        }
        __syncthreads();
    }

    // epilogue: R[m][n] = acc + b_out[n]
    size_t Rbase = (size_t)bt * 128 * Cq + bn * 128;
    #pragma unroll
    for (int mt = 0; mt < 2; ++mt) {
        int r0 = mbase + mt * 16 + g;
        #pragma unroll
        for (int nt = 0; nt < 8; ++nt) {
            int nl = nbase + nt * 8 + 2 * tig;
            float2 v0 = make_float2(acc[mt][nt][0] + sbo[nl],
                                    acc[mt][nt][1] + sbo[nl + 1]);
            float2 v1 = make_float2(acc[mt][nt][2] + sbo[nl],
                                    acc[mt][nt][3] + sbo[nl + 1]);
            *(float2*)(g_R + Rbase + (size_t)r0 * Cq + nl)       = v0;
            *(float2*)(g_R + Rbase + (size_t)(r0 + 8) * Cq + nl) = v1;
        }
    }
}

// ---------------- kernel 4: out[b,d,h,t,s] = sum_f qk[b,d,h,t,f]*R[b,t,s,h,f]
__global__ __launch_bounds__(256) void einsum_tc(const float* __restrict__ qk,
                                                 float* __restrict__ out) {
    __shared__ unsigned As[128][68];   // [d][f]
    __shared__ unsigned Bs[128][68];   // [s][f]

    int tid = threadIdx.x;
    int bid = blockIdx.x;              // B*H*T*2 = 4096
    int dchunk = bid & 1; int rest = bid >> 1;
    int t = rest & 127; rest >>= 7;
    int h = rest & 7;   int b = rest >> 3;

    const size_t dstr = (size_t)Hq * Tq * Fq;   // 65536
    const float* qk_base = qk + ((((size_t)b * Dq + dchunk * 128) * Hq + h) * Tq + t) * Fq;
    const float* R_base  = g_R + (size_t)(b * Tq + t) * Tq * Cq + h * Fq;

    #pragma unroll
    for (int r = 0; r < 8; ++r) {
        int idx = tid + r * 256;
        int row = idx >> 4, f4 = (idx & 15) * 4;
        float4 v = *(const float4*)(qk_base + (size_t)row * dstr + f4);
        uint4 o;
        o.x = f2tf32(v.x); o.y = f2tf32(v.y); o.z = f2tf32(v.z); o.w = f2tf32(v.w);
        *(uint4*)&As[row][f4] = o;
    }
    #pragma unroll
    for (int r = 0; r < 8; ++r) {
        int idx = tid + r * 256;
        int row = idx >> 4, f4 = (idx & 15) * 4;
        float4 v = *(const float4*)(R_base + (size_t)row * Cq + f4);
        uint4 o;
        o.x = f2tf32(v.x); o.y = f2tf32(v.y); o.z = f2tf32(v.z); o.w = f2tf32(v.w);
        *(uint4*)&Bs[row][f4] = o;
    }
    __syncthreads();

    int lane = tid & 31, warp = tid >> 5;
    int g = lane >> 2, tig = lane & 3;
    int wm = warp >> 1, wn = warp & 1;
    int mbase = wm * 32, nbase = wn * 64;

    float acc[2][8][4] = {};

    #pragma unroll
    for (int q = 0; q < 8; ++q) {
        int kk = q * 8;
        unsigned a[2][4];
        #pragma unroll
        for (int mt = 0; mt < 2; ++mt) {
            int m = mbase + mt * 16 + g;
            a[mt][0] = As[m][kk + tig];
            a[mt][1] = As[m + 8][kk + tig];
            a[mt][2] = As[m][kk + tig + 4];
            a[mt][3] = As[m + 8][kk + tig + 4];
        }
        #pragma unroll
        for (int nt = 0; nt < 8; ++nt) {
            int n = nbase + nt * 8 + g;
            unsigned b0 = Bs[n][kk + tig];
            unsigned b1 = Bs[n][kk + tig + 4];
            mma8(acc[0][nt], a[0], b0, b1);
            mma8(acc[1][nt], a[1], b0, b1);
        }
    }

    const size_t ostr = (size_t)Hq * Tq * Tq;   // 131072
    float* out_base = out + ((((size_t)b * Dq + dchunk * 128) * Hq + h) * Tq + t) * Tq;
    #pragma unroll
    for (int mt = 0; mt < 2; ++mt) {
        int r0 = mbase + mt * 16 + g;
        #pragma unroll
        for (int nt = 0; nt < 8; ++nt) {
            int nl = nbase + nt * 8 + 2 * tig;
            *(float2*)(out_base + (size_t)r0 * ostr + nl) =
                make_float2(acc[mt][nt][0], acc[mt][nt][1]);
            *(float2*)(out_base + (size_t)(r0 + 8) * ostr + nl) =
                make_float2(acc[mt][nt][2], acc[mt][nt][3]);
        }
    }
}

// ---------------------------------------------------------------------------
extern "C" void kernel_launch(void* const* d_in, const int* in_sizes, int n_in,
                              void* d_out, int out_size) {
    const float* qk     = (const float*)d_in[0];
    const float* temb   = (const float*)d_in[1];
    const int*   pd     = (const int*)  d_in[2];
    const float* w_dist = (const float*)d_in[3];
    const float* b_dist = (const float*)d_in[4];
    const float* w_time = (const float*)d_in[5];
    const float* b_time = (const float*)d_in[6];
    const float* w_out  = (const float*)d_in[7];
    const float* b_out  = (const float*)d_in[8];
    float* out = (float*)d_out;

    tp_kernel <<<Bq * Tq, Cq>>>(temb, w_time, b_time);
    lut_kernel<<<NDIST,  Cq>>>(w_dist, b_dist);
    cvtB_kernel<<<Cq, 256>>>(w_out);
    dim3 gR(Cq / 128, (Bq * Tq * Tq) / 128);
    gemmR_tc<<<gR, 256>>>(pd, b_out);
    einsum_tc<<<Bq * Hq * Tq * 2, 256>>>(qk, out);
}